// round 16
// baseline (speedup 1.0000x reference)
#include <cuda_runtime.h>

// Shapes: re, gt are (B=32, C=10, H=192, W=320) float32, contiguous.
#define NB     32
#define NC     10
#define HW     61440                  // 192*320 pixels per channel
#define HW4    15360                  // float4 groups per channel
#define N4     (NB*HW4)               // 491520 groups total
#define NPIX   (NB*HW)                // 1966080 pixels
#define BLK    256
#define GRID1  (N4/BLK)               // 1920 blocks for pass 1
#define GRID2  480                    // pass 2 blocks
#define NACC   5
#define EPSF   6e-8f

// [0]=num_pos [1]=focal_sum [2]=A (pos+height+const) [3]=B [4]=C
__device__ float g_acc[NACC];          // zero-init; last K2 block re-zeros
__device__ int   g_nmv   = 0;          // worklist length (K1 builds, K2 resets)
__device__ unsigned int g_done = 0;    // K2 completion counter
__device__ int   g_idx[NPIX];          // mv pixel worklist (7.5 MB static)

__device__ __forceinline__ float sl1(float d) {
    float ad = fabsf(d);
    return ad < 1.0f ? 0.5f * d * d : ad - 0.5f;
}

__device__ __forceinline__ float c4(const float4& v, int j) {
    return j == 0 ? v.x : (j == 1 ? v.y : (j == 2 ? v.z : v.w));
}

// ---------------- Pass 1: focal + mv compaction (reads ch0 only) ------------
__global__ void __launch_bounds__(BLK)
k1_focal_compact(const float* __restrict__ re, const float* __restrict__ gt) {
    const float4* __restrict__ re4 = (const float4*)re;
    const float4* __restrict__ gt4 = (const float4*)gt;

    const int i4  = blockIdx.x * BLK + threadIdx.x;   // float4 group < N4
    const int b   = i4 / HW4;
    const int hw4 = i4 - b * HW4;
    const float4 G0 = gt4[b * (NC * HW4) + hw4];
    const float4 R0 = re4[b * (NC * HW4) + hw4];

    float a_np = 0.f, a_f = 0.f;
    unsigned mvm = 0;
#pragma unroll
    for (int j = 0; j < 4; j++) {
        const float g = c4(G0, j);
        const float r = c4(R0, j);
        const bool  m0  = (g >= 0.0f);
        const bool  pos = (g >= 0.1f);                // FOCAL_THR, implies m0
        const float safe = fminf(fmaxf(r, 1e-6f), 1.0f - 1e-6f);
        const float larg = pos ? (safe + EPSF) : (1.0f + EPSF - safe);
        const float lg   = __logf(larg);              // larg > 0 always
        const float d0   = g - r;
        const float om   = 1.0f - g;
        const float om2  = om * om;
        float w = pos ? (d0 * d0) : (r * r * (om2 * om2));
        if (!m0) w = 0.0f;
        a_f -= w * lg;
        if (pos) a_np += 1.0f;
        if (g == 1.0f) mvm |= 1u << j;
    }

    // Warp-aggregated compaction of mv pixel indices.
    const int lane = threadIdx.x & 31;
    const int nm = __popc(mvm);
    int pre = nm;
#pragma unroll
    for (int o = 1; o < 32; o <<= 1) {
        int v = __shfl_up_sync(0xffffffffu, pre, o);
        if (lane >= o) pre += v;
    }
    const int excl  = pre - nm;
    const int total = __shfl_sync(0xffffffffu, pre, 31);
    int basew = 0;
    if (lane == 31 && total > 0) basew = atomicAdd(&g_nmv, total);
    basew = __shfl_sync(0xffffffffu, basew, 31);
    int pos = basew + excl;
    const int p0 = b * HW + hw4 * 4;                  // pixel index of j=0
#pragma unroll
    for (int j = 0; j < 4; j++)
        if ((mvm >> j) & 1u) g_idx[pos++] = p0 + j;

    // Block-reduce the two focal accumulators -> global atomics.
    __shared__ float sh[BLK/32][2];
    const int warp = threadIdx.x >> 5;
    float v0 = a_np, v1 = a_f;
#pragma unroll
    for (int o = 16; o > 0; o >>= 1) {
        v0 += __shfl_down_sync(0xffffffffu, v0, o);
        v1 += __shfl_down_sync(0xffffffffu, v1, o);
    }
    if (lane == 0) { sh[warp][0] = v0; sh[warp][1] = v1; }
    __syncthreads();
    if (threadIdx.x < 2) {
        float v = 0.f;
#pragma unroll
        for (int w = 0; w < BLK/32; w++) v += sh[w][threadIdx.x];
        atomicAdd(&g_acc[threadIdx.x], v);
    }
}

// ---------------- Pass 2: gather mv pixels only, finalize -------------------
__global__ void __launch_bounds__(BLK)
k2_gather(const float* __restrict__ re, const float* __restrict__ gt,
          float* __restrict__ out) {
    const int n = g_nmv;                              // stable during K2
    float a_A = 0.f, a_B = 0.f, a_C = 0.f;

    for (int w = blockIdx.x * BLK + threadIdx.x; w < n; w += GRID2 * BLK) {
        const int p  = g_idx[w];
        const int b  = p / HW;
        const int hw = p - b * HW;
        const float* __restrict__ gp = gt + (size_t)b * (NC * HW) + hw;
        const float* __restrict__ rp = re + (size_t)b * (NC * HW) + hw;

        // 18 independent scalar loads, all front-batched (one window).
        const float g1 = gp[1*HW], g2 = gp[2*HW], g3 = gp[3*HW];
        const float g4 = gp[4*HW], g5 = gp[5*HW], g6 = gp[6*HW];
        const float g7 = gp[7*HW], g8 = gp[8*HW], g9 = gp[9*HW];
        const float r1 = rp[1*HW], r2 = rp[2*HW], r3 = rp[3*HW];
        const float r4 = rp[4*HW], r5 = rp[5*HW], r6 = rp[6*HW];
        const float r7 = rp[7*HW], r8 = rp[8*HW], r9 = rp[9*HW];

        // pos (0.5 = POS_W/2) + height (0.1 = LEN_W) + const (0.5 = CONST_W)
        const float c1 = 1.0f - r5*r5 - r4*r4;
        const float c2 = 1.0f - r8*r8 - r7*r7;
        a_A += 0.5f * (sl1(r1 - g1) + sl1(r2 - g2))
             + 0.1f * sl1(r9 - g9)
             + 0.5f * (c1*c1 + c2*c2);

        // length (0.05 = LEN_W/2) + trig (0.5 = TRIG_W/2), straight / crossed
        const float d44 = r4 - g4, d77 = r7 - g7;
        const float d55 = r5 - g5, d88 = r8 - g8;
        a_B += 0.05f * (sl1(r3 - g3) + sl1(r6 - g6))
             + 0.5f  * (d44*d44 + d77*d77 + d55*d55 + d88*d88);
        const float d47 = r4 - g7, d74 = r7 - g4;
        const float d58 = r5 - g8, d85 = r8 - g5;
        a_C += 0.05f * (sl1(r3 - g6) + sl1(r6 - g3))
             + 0.5f  * (d47*d47 + d74*d74 + d58*d58 + d85*d85);
    }

    // Block reduction -> global atomics.
    __shared__ float sh[BLK/32][3];
    const int lane = threadIdx.x & 31;
    const int warp = threadIdx.x >> 5;
    float v0 = a_A, v1 = a_B, v2 = a_C;
#pragma unroll
    for (int o = 16; o > 0; o >>= 1) {
        v0 += __shfl_down_sync(0xffffffffu, v0, o);
        v1 += __shfl_down_sync(0xffffffffu, v1, o);
        v2 += __shfl_down_sync(0xffffffffu, v2, o);
    }
    if (lane == 0) { sh[warp][0] = v0; sh[warp][1] = v1; sh[warp][2] = v2; }
    __syncthreads();
    if (threadIdx.x < 3) {
        float v = 0.f;
#pragma unroll
        for (int w = 0; w < BLK/32; w++) v += sh[w][threadIdx.x];
        atomicAdd(&g_acc[2 + threadIdx.x], v);
    }

    // Last-block-done: finalize and reset all state for the next replay.
    __shared__ bool is_last;
    __threadfence();
    __syncthreads();
    if (threadIdx.x == 0) {
        unsigned int old = atomicAdd(&g_done, 1u);
        is_last = (old == GRID2 - 1);
    }
    __syncthreads();
    if (!is_last) return;

    if (threadIdx.x == 0) {
        __threadfence();

        const float nv      = (float)n;
        const float num_pos = g_acc[0];
        const float S       = g_acc[1];
        const float focal = (num_pos == 0.0f) ? S : S / num_pos;
        out[0] = focal + (g_acc[2] + fminf(g_acc[3], g_acc[4])) / nv;

#pragma unroll
        for (int k = 0; k < NACC; k++) g_acc[k] = 0.0f;
        g_nmv  = 0;
        g_done = 0;
    }
}

extern "C" void kernel_launch(void* const* d_in, const int* in_sizes, int n_in,
                              void* d_out, int out_size) {
    const float* re = (const float*)d_in[0];
    const float* gt = (const float*)d_in[1];
    float* out = (float*)d_out;

    k1_focal_compact<<<GRID1, BLK>>>(re, gt);
    k2_gather<<<GRID2, BLK>>>(re, gt, out);
}

// round 17
// speedup vs baseline: 1.0605x; 1.0605x over previous
#include <cuda_runtime.h>

// Shapes: re, gt are (B=32, C=10, H=192, W=320) float32, contiguous.
#define NB     32
#define NC     10
#define HW     61440                  // 192*320 pixels per channel
#define HW4    15360                  // float4 groups per channel
#define N4     (NB*HW4)               // 491520 groups total
#define NPIX   (NB*HW)                // 1966080 pixels
#define BLK    256
#define GRID1  960                    // pass 1: 2 groups/thread
#define STR1   (GRID1*BLK)            // 245760
#define GRID2  960                    // pass 2 blocks
#define NACC   5
#define EPSF   6e-8f

// [0]=num_pos [1]=focal_sum [2]=A (pos+height+const) [3]=B [4]=C
__device__ float g_acc[NACC];          // zero-init; last K2 block re-zeros
__device__ int   g_nmv   = 0;          // worklist length (K1 builds, K2 resets)
__device__ unsigned int g_done = 0;    // K2 completion counter
__device__ int   g_idx[NPIX];          // mv pixel worklist (7.5 MB static)

__device__ __forceinline__ float sl1(float d) {
    float ad = fabsf(d);
    return ad < 1.0f ? 0.5f * d * d : ad - 0.5f;
}

__device__ __forceinline__ float c4(const float4& v, int j) {
    return j == 0 ? v.x : (j == 1 ? v.y : (j == 2 ? v.z : v.w));
}

// ---------------- Pass 1: focal + mv compaction (reads ch0 only) ------------
__global__ void __launch_bounds__(BLK)
k1_focal_compact(const float* __restrict__ re, const float* __restrict__ gt) {
    const float4* __restrict__ re4 = (const float4*)re;
    const float4* __restrict__ gt4 = (const float4*)gt;

    const int t = blockIdx.x * BLK + threadIdx.x;

    // Both groups' loads in one window (4x LDG.128).
    int p0[2];
    float4 G0[2], R0[2];
#pragma unroll
    for (int k = 0; k < 2; k++) {
        const int i4  = t + k * STR1;                 // float4 group < N4
        const int b   = i4 / HW4;
        const int hw4 = i4 - b * HW4;
        p0[k] = b * HW + hw4 * 4;                     // pixel index of lane j=0
        G0[k] = gt4[b * (NC * HW4) + hw4];
        R0[k] = re4[b * (NC * HW4) + hw4];
    }

    float a_np = 0.f, a_f = 0.f;
    unsigned mvm[2] = {0u, 0u};
#pragma unroll
    for (int k = 0; k < 2; k++) {
#pragma unroll
        for (int j = 0; j < 4; j++) {
            const float g = c4(G0[k], j);
            const float r = c4(R0[k], j);
            const bool  m0  = (g >= 0.0f);
            const bool  pos = (g >= 0.1f);            // FOCAL_THR, implies m0
            const float safe = fminf(fmaxf(r, 1e-6f), 1.0f - 1e-6f);
            const float larg = pos ? (safe + EPSF) : (1.0f + EPSF - safe);
            const float lg   = __logf(larg);          // larg > 0 always
            const float d0   = g - r;
            const float om   = 1.0f - g;
            const float om2  = om * om;
            float w = pos ? (d0 * d0) : (r * r * (om2 * om2));
            if (!m0) w = 0.0f;
            a_f -= w * lg;
            if (pos) a_np += 1.0f;
            if (g == 1.0f) mvm[k] |= 1u << j;
        }
    }

    // ONE warp-aggregated compaction round for both groups (8 candidate px).
    const int lane = threadIdx.x & 31;
    const int nm = __popc(mvm[0]) + __popc(mvm[1]);
    int pre = nm;
#pragma unroll
    for (int o = 1; o < 32; o <<= 1) {
        int v = __shfl_up_sync(0xffffffffu, pre, o);
        if (lane >= o) pre += v;
    }
    const int excl  = pre - nm;
    const int total = __shfl_sync(0xffffffffu, pre, 31);
    int basew = 0;
    if (lane == 31 && total > 0) basew = atomicAdd(&g_nmv, total);
    basew = __shfl_sync(0xffffffffu, basew, 31);
    int wpos = basew + excl;
#pragma unroll
    for (int k = 0; k < 2; k++)
#pragma unroll
        for (int j = 0; j < 4; j++)
            if ((mvm[k] >> j) & 1u) g_idx[wpos++] = p0[k] + j;

    // Block-reduce the two focal accumulators -> global atomics.
    __shared__ float sh[BLK/32][2];
    const int warp = threadIdx.x >> 5;
    float v0 = a_np, v1 = a_f;
#pragma unroll
    for (int o = 16; o > 0; o >>= 1) {
        v0 += __shfl_down_sync(0xffffffffu, v0, o);
        v1 += __shfl_down_sync(0xffffffffu, v1, o);
    }
    if (lane == 0) { sh[warp][0] = v0; sh[warp][1] = v1; }
    __syncthreads();
    if (threadIdx.x < 2) {
        float v = 0.f;
#pragma unroll
        for (int w = 0; w < BLK/32; w++) v += sh[w][threadIdx.x];
        atomicAdd(&g_acc[threadIdx.x], v);
    }
}

// ---------------- Pass 2: gather mv pixels only, finalize -------------------
__global__ void __launch_bounds__(BLK)
k2_gather(const float* __restrict__ re, const float* __restrict__ gt,
          float* __restrict__ out) {
    const int n = g_nmv;                              // stable during K2
    float a_A = 0.f, a_B = 0.f, a_C = 0.f;

    for (int w = blockIdx.x * BLK + threadIdx.x; w < n; w += GRID2 * BLK) {
        const int p  = g_idx[w];
        const int b  = p / HW;
        const int hw = p - b * HW;
        const float* __restrict__ gp = gt + (size_t)b * (NC * HW) + hw;
        const float* __restrict__ rp = re + (size_t)b * (NC * HW) + hw;

        // 18 independent scalar loads, all front-batched (one window).
        const float g1 = gp[1*HW], g2 = gp[2*HW], g3 = gp[3*HW];
        const float g4 = gp[4*HW], g5 = gp[5*HW], g6 = gp[6*HW];
        const float g7 = gp[7*HW], g8 = gp[8*HW], g9 = gp[9*HW];
        const float r1 = rp[1*HW], r2 = rp[2*HW], r3 = rp[3*HW];
        const float r4 = rp[4*HW], r5 = rp[5*HW], r6 = rp[6*HW];
        const float r7 = rp[7*HW], r8 = rp[8*HW], r9 = rp[9*HW];

        // pos (0.5 = POS_W/2) + height (0.1 = LEN_W) + const (0.5 = CONST_W)
        const float c1 = 1.0f - r5*r5 - r4*r4;
        const float c2 = 1.0f - r8*r8 - r7*r7;
        a_A += 0.5f * (sl1(r1 - g1) + sl1(r2 - g2))
             + 0.1f * sl1(r9 - g9)
             + 0.5f * (c1*c1 + c2*c2);

        // length (0.05 = LEN_W/2) + trig (0.5 = TRIG_W/2), straight / crossed
        const float d44 = r4 - g4, d77 = r7 - g7;
        const float d55 = r5 - g5, d88 = r8 - g8;
        a_B += 0.05f * (sl1(r3 - g3) + sl1(r6 - g6))
             + 0.5f  * (d44*d44 + d77*d77 + d55*d55 + d88*d88);
        const float d47 = r4 - g7, d74 = r7 - g4;
        const float d58 = r5 - g8, d85 = r8 - g5;
        a_C += 0.05f * (sl1(r3 - g6) + sl1(r6 - g3))
             + 0.5f  * (d47*d47 + d74*d74 + d58*d58 + d85*d85);
    }

    // Block reduction -> global atomics.
    __shared__ float sh[BLK/32][3];
    const int lane = threadIdx.x & 31;
    const int warp = threadIdx.x >> 5;
    float v0 = a_A, v1 = a_B, v2 = a_C;
#pragma unroll
    for (int o = 16; o > 0; o >>= 1) {
        v0 += __shfl_down_sync(0xffffffffu, v0, o);
        v1 += __shfl_down_sync(0xffffffffu, v1, o);
        v2 += __shfl_down_sync(0xffffffffu, v2, o);
    }
    if (lane == 0) { sh[warp][0] = v0; sh[warp][1] = v1; sh[warp][2] = v2; }
    __syncthreads();
    if (threadIdx.x < 3) {
        float v = 0.f;
#pragma unroll
        for (int w = 0; w < BLK/32; w++) v += sh[w][threadIdx.x];
        atomicAdd(&g_acc[2 + threadIdx.x], v);
    }

    // Last-block-done: finalize and reset all state for the next replay.
    __shared__ bool is_last;
    __threadfence();
    __syncthreads();
    if (threadIdx.x == 0) {
        unsigned int old = atomicAdd(&g_done, 1u);
        is_last = (old == GRID2 - 1);
    }
    __syncthreads();
    if (!is_last) return;

    if (threadIdx.x == 0) {
        __threadfence();

        const float nv      = (float)n;
        const float num_pos = g_acc[0];
        const float S       = g_acc[1];
        const float focal = (num_pos == 0.0f) ? S : S / num_pos;
        out[0] = focal + (g_acc[2] + fminf(g_acc[3], g_acc[4])) / nv;

#pragma unroll
        for (int k = 0; k < NACC; k++) g_acc[k] = 0.0f;
        g_nmv  = 0;
        g_done = 0;
    }
}

extern "C" void kernel_launch(void* const* d_in, const int* in_sizes, int n_in,
                              void* d_out, int out_size) {
    const float* re = (const float*)d_in[0];
    const float* gt = (const float*)d_in[1];
    float* out = (float*)d_out;

    k1_focal_compact<<<GRID1, BLK>>>(re, gt);
    k2_gather<<<GRID2, BLK>>>(re, gt, out);
}